// round 14
// baseline (speedup 1.0000x reference)
#include <cuda_runtime.h>
#include <cuda_fp16.h>
#include <math.h>

// ---------------- problem constants ----------------
#define NMAX 50048            // N = 50000 nodes (padded)
#define EMAX 1600512
#define FIN  512
#define D1   64               // H1*hid = 8*8
#define H1N  8
#define D2   40               // C (H2=1)
#define SCB  196              // scan blocks: 196*256 = 50176 >= 50000

// ---------------- scratch (device globals; no allocation allowed) ----------------
__device__ __align__(16) float g_h1 [NMAX * D1];   // x @ W1
__device__ __align__(16) float g_as1[NMAX * H1N];
__device__ __align__(16) float g_ad1[NMAX * H1N];
__device__ __align__(16) float g_z1 [NMAX * D1];   // relu(agg + b1): GEMM2 input
__device__ __align__(16) float g_h2 [NMAX * D2];
__device__ __align__(16) float g_as2[NMAX];
__device__ __align__(16) float g_ad2[NMAX];
// CSR-by-dst (built once per launch, shared by both layers)
__device__ int g_cnt[NMAX];      // zero-init at module load; scanB re-zeros after use
__device__ int g_row[NMAX + 1];
__device__ int g_cur[NMAX];
__device__ int g_part[SCB + 1];
__device__ int g_srt[EMAX];      // src ids, grouped by dst

__device__ __forceinline__ unsigned tf32_of(float x) {
    unsigned r;
    asm("cvt.rna.tf32.f32 %0, %1;" : "=r"(r) : "f"(x));
    return r;
}
__device__ __forceinline__ float lrelu(float v) { return (v >= 0.f) ? v : 0.2f * v; }

// ---------------- CSR build ------------------------------------------------------
__global__ void k_hist(const int* __restrict__ ei, int E) {
    int i4 = (blockIdx.x * blockDim.x + threadIdx.x) * 4;
    if (i4 + 3 < E) {
        int4 d = *(const int4*)(ei + E + i4);
        atomicAdd(&g_cnt[d.x], 1);
        atomicAdd(&g_cnt[d.y], 1);
        atomicAdd(&g_cnt[d.z], 1);
        atomicAdd(&g_cnt[d.w], 1);
    } else {
        for (int k = i4; k < E; k++) atomicAdd(&g_cnt[__ldg(ei + E + k)], 1);
    }
}
// phase A: per-block chunk sums
__global__ void k_scanA() {
    __shared__ int sh[256];
    int t = threadIdx.x, b = blockIdx.x;
    int i = b * 256 + t;
    int v = (i < NMAX) ? g_cnt[i] : 0;
    sh[t] = v;
    __syncthreads();
#pragma unroll
    for (int off = 128; off; off >>= 1) {
        if (t < off) sh[t] += sh[t + off];
        __syncthreads();
    }
    if (t == 0) g_part[b] = sh[0];
}
// phase B: in-block scan of partials + local scan -> row/cur; resets g_cnt
__global__ void k_scanB(int Nn) {
    __shared__ int part[256];
    __shared__ int sh[256];
    int t = threadIdx.x, b = blockIdx.x;
    part[t] = (t < SCB) ? g_part[t] : 0;
    __syncthreads();
    for (int off = 1; off < 256; off <<= 1) {
        int u = (t >= off) ? part[t - off] : 0;
        __syncthreads();
        part[t] += u;
        __syncthreads();
    }
    int base = (b == 0) ? 0 : part[b - 1];

    int i = b * 256 + t;
    int v = (i < NMAX) ? g_cnt[i] : 0;
    sh[t] = v;
    __syncthreads();
    for (int off = 1; off < 256; off <<= 1) {
        int u = (t >= off) ? sh[t - off] : 0;
        __syncthreads();
        sh[t] += u;
        __syncthreads();
    }
    int excl = sh[t] - v + base;
    if (i <= Nn) {
        g_row[i] = excl;
        if (i < Nn) g_cur[i] = excl;
    }
    if (i < NMAX) g_cnt[i] = 0;   // reset for the next graph replay
}
__global__ void k_scatter(const int* __restrict__ ei, int E) {
    int i = blockIdx.x * blockDim.x + threadIdx.x;
    if (i >= E) return;
    int s = __ldg(ei + i), d = __ldg(ei + E + i);
    int p = atomicAdd(&g_cur[d], 1);
    g_srt[p] = s;
}

// ---------------- GEMM1 (tf32 MMA) + fused att1 ---------------------------------
// h1 = x @ W1; also as1/ad1 = per-head dots with att vectors (epilogue shfl).
__global__ void k_gemm1(const float* __restrict__ A, const float* __restrict__ B,
                        const float* __restrict__ asrc, const float* __restrict__ adst,
                        int M) {
    __shared__ __align__(16) float As[128 * 36];
    __shared__ __align__(16) float Bs[64 * 36];
    const int tid  = threadIdx.x;
    const int warp = tid >> 5, lane = tid & 31;
    const int row0 = blockIdx.x * 128;
    const int lr = lane >> 2, lc = lane & 3;

    float acc[8][4];
#pragma unroll
    for (int nt = 0; nt < 8; nt++)
#pragma unroll
        for (int j = 0; j < 4; j++) acc[nt][j] = 0.f;

    for (int k0 = 0; k0 < FIN; k0 += 32) {
#pragma unroll
        for (int i = 0; i < 4; i++) {
            int idx = tid + i * 256;
            int r = idx >> 3, c4 = idx & 7;
            float4 v = make_float4(0.f, 0.f, 0.f, 0.f);
            int gr = row0 + r;
            if (gr < M) v = *(const float4*)(A + (size_t)gr * FIN + k0 + c4 * 4);
            int c = c4 * 4;
            As[r * 36 + ((c + 0) & 7) * 4 + ((c + 0) >> 3)] = __uint_as_float(tf32_of(v.x));
            As[r * 36 + ((c + 1) & 7) * 4 + ((c + 1) >> 3)] = __uint_as_float(tf32_of(v.y));
            As[r * 36 + ((c + 2) & 7) * 4 + ((c + 2) >> 3)] = __uint_as_float(tf32_of(v.z));
            As[r * 36 + ((c + 3) & 7) * 4 + ((c + 3) >> 3)] = __uint_as_float(tf32_of(v.w));
        }
#pragma unroll
        for (int i = 0; i < 2; i++) {
            int idx = tid + i * 256;
            int k = idx >> 4, c4 = idx & 15;
            float4 v = *(const float4*)(B + (size_t)(k0 + k) * D1 + c4 * 4);
            int kk = ((k & 7) << 2) + (k >> 3);
            Bs[(c4 * 4 + 0) * 36 + kk] = __uint_as_float(tf32_of(v.x));
            Bs[(c4 * 4 + 1) * 36 + kk] = __uint_as_float(tf32_of(v.y));
            Bs[(c4 * 4 + 2) * 36 + kk] = __uint_as_float(tf32_of(v.z));
            Bs[(c4 * 4 + 3) * 36 + kk] = __uint_as_float(tf32_of(v.w));
        }
        __syncthreads();

        const float* ab = As + (warp * 16 + lr) * 36;
        float4 a00 = *(const float4*)(ab +        lc * 4);
        float4 a10 = *(const float4*)(ab + 8*36 + lc * 4);
        float4 a01 = *(const float4*)(ab +        (lc + 4) * 4);
        float4 a11 = *(const float4*)(ab + 8*36 + (lc + 4) * 4);
        const unsigned* a00u = (const unsigned*)&a00;
        const unsigned* a10u = (const unsigned*)&a10;
        const unsigned* a01u = (const unsigned*)&a01;
        const unsigned* a11u = (const unsigned*)&a11;

#pragma unroll
        for (int nt = 0; nt < 8; nt++) {
            const float* bb = Bs + (nt * 8 + lr) * 36;
            float4 b0v = *(const float4*)(bb + lc * 4);
            float4 b1v = *(const float4*)(bb + (lc + 4) * 4);
            const unsigned* b0u = (const unsigned*)&b0v;
            const unsigned* b1u = (const unsigned*)&b1v;
#pragma unroll
            for (int ks = 0; ks < 4; ks++) {
                asm volatile(
                    "mma.sync.aligned.m16n8k8.row.col.f32.tf32.tf32.f32 "
                    "{%0,%1,%2,%3}, {%4,%5,%6,%7}, {%8,%9}, {%0,%1,%2,%3};"
                    : "+f"(acc[nt][0]), "+f"(acc[nt][1]), "+f"(acc[nt][2]), "+f"(acc[nt][3])
                    : "r"(a00u[ks]), "r"(a10u[ks]), "r"(a01u[ks]), "r"(a11u[ks]),
                      "r"(b0u[ks]), "r"(b1u[ks]));
            }
        }
        __syncthreads();
    }

    int gr = row0 + warp * 16 + lr;
#pragma unroll
    for (int nt = 0; nt < 8; nt++) {
        int col = nt * 8 + lc * 2;
        if (gr < M)     *(float2*)(g_h1 + (size_t)gr * D1 + col)       = make_float2(acc[nt][0], acc[nt][1]);
        if (gr + 8 < M) *(float2*)(g_h1 + (size_t)(gr + 8) * D1 + col) = make_float2(acc[nt][2], acc[nt][3]);

        // fused att1: head nt covers cols nt*8..nt*8+7; reduce across the lc quad
        float w0s = __ldg(asrc + nt * 8 + lc * 2), w1s = __ldg(asrc + nt * 8 + lc * 2 + 1);
        float w0d = __ldg(adst + nt * 8 + lc * 2), w1d = __ldg(adst + nt * 8 + lc * 2 + 1);
        float pSA = acc[nt][0] * w0s + acc[nt][1] * w1s;
        float pDA = acc[nt][0] * w0d + acc[nt][1] * w1d;
        float pSB = acc[nt][2] * w0s + acc[nt][3] * w1s;
        float pDB = acc[nt][2] * w0d + acc[nt][3] * w1d;
#pragma unroll
        for (int off = 1; off <= 2; off <<= 1) {
            pSA += __shfl_xor_sync(0xffffffffu, pSA, off);
            pDA += __shfl_xor_sync(0xffffffffu, pDA, off);
            pSB += __shfl_xor_sync(0xffffffffu, pSB, off);
            pDB += __shfl_xor_sync(0xffffffffu, pDB, off);
        }
        if (lc == 0) {
            if (gr < M)     { g_as1[gr * H1N + nt] = pSA;       g_ad1[gr * H1N + nt] = pDA; }
            if (gr + 8 < M) { g_as1[(gr + 8) * H1N + nt] = pSB; g_ad1[(gr + 8) * H1N + nt] = pDB; }
        }
    }
}

// ---------------- layer-1 aggregate: HALF-WARP per node, idx prefetch -----------
// half h owns node w*2+h; lane ll (0..15) owns features 4ll..4ll+3; head = ll>>1.
__global__ void k_agg1(const float* __restrict__ b1, int Nn) {
    int w = (blockIdx.x * blockDim.x + threadIdx.x) >> 5;
    int lane = threadIdx.x & 31;
    if (w * 2 >= Nn) return;              // uniform whole-warp exit
    int half = lane >> 4;
    int ll = lane & 15;
    int hh = ll >> 1;
    int n = w * 2 + half;
    bool valid = (n < Nn);
    int nc = valid ? n : (Nn - 1);

    float adh = g_ad1[nc * H1N + hh];

    // self-loop
    float ex = __expf(lrelu(g_as1[nc * H1N + hh] + adh));
    float4 hv = *(const float4*)(g_h1 + (size_t)nc * D1 + ll * 4);
    float ax = ex * hv.x, ay = ex * hv.y, az = ex * hv.z, aw = ex * hv.w;
    float den = ((ll & 1) == 0) ? ex : 0.f;

    int j = g_row[nc], end = g_row[nc + 1];
    int p0 = 0, p1 = 0;
    bool have = (j + 2 <= end);
    if (have) { p0 = __ldg(g_srt + j); p1 = __ldg(g_srt + j + 1); }
    while (have) {
        int jn = j + 2;
        bool haven = (jn + 2 <= end);
        int n0 = 0, n1 = 0;
        if (haven) { n0 = __ldg(g_srt + jn); n1 = __ldg(g_srt + jn + 1); }  // prefetch
        float e0 = __ldg(g_as1 + p0 * H1N + hh) + adh;
        float e1 = __ldg(g_as1 + p1 * H1N + hh) + adh;
        float4 v0 = *(const float4*)(g_h1 + (size_t)p0 * D1 + ll * 4);
        float4 v1 = *(const float4*)(g_h1 + (size_t)p1 * D1 + ll * 4);
        float x0 = __expf(lrelu(e0)), x1 = __expf(lrelu(e1));
        ax += x0 * v0.x + x1 * v1.x;
        ay += x0 * v0.y + x1 * v1.y;
        az += x0 * v0.z + x1 * v1.z;
        aw += x0 * v0.w + x1 * v1.w;
        if ((ll & 1) == 0) den += x0 + x1;
        j = jn; p0 = n0; p1 = n1; have = haven;
    }
    for (; j < end; j++) {
        int s0 = __ldg(g_srt + j);
        float x0 = __expf(lrelu(__ldg(g_as1 + s0 * H1N + hh) + adh));
        float4 v0 = *(const float4*)(g_h1 + (size_t)s0 * D1 + ll * 4);
        ax += x0 * v0.x; ay += x0 * v0.y; az += x0 * v0.z; aw += x0 * v0.w;
        if ((ll & 1) == 0) den += x0;
    }

    __syncwarp();
    float dh = __shfl_sync(0xffffffffu, den, (lane & 16) | (ll & 0xe));
    float inv = 1.f / (dh + 1e-16f);
    float4 bv = *(const float4*)(b1 + ll * 4);
    if (valid) {
        float4 z;
        z.x = fmaxf(ax * inv + bv.x, 0.f);
        z.y = fmaxf(ay * inv + bv.y, 0.f);
        z.z = fmaxf(az * inv + bv.z, 0.f);
        z.w = fmaxf(aw * inv + bv.w, 0.f);
        *(float4*)(g_z1 + (size_t)n * D1 + ll * 4) = z;
    }
}

// ---------------- GEMM2 + fused att2: h2 = z1 @ W2 ------------------------------
__global__ void k_gemm2(const float* __restrict__ W2,
                        const float* __restrict__ s2v, const float* __restrict__ d2v,
                        int M) {
    __shared__ __align__(16) float As[64][65];
    __shared__ __align__(16) float Bs[64][D2];
    __shared__ float sS[64][4], sD[64][4];
    const int tid = threadIdx.x;
    const int row0 = blockIdx.x * 64;

    for (int idx = tid; idx < 64 * D2; idx += 256)
        Bs[idx / D2][idx % D2] = W2[idx];

#pragma unroll
    for (int i = 0; i < 4; i++) {
        int idx = tid + i * 256;
        int r = idx >> 4, c = idx & 15;
        int gr = row0 + r;
        float4 v = make_float4(0.f, 0.f, 0.f, 0.f);
        if (gr < M) v = *(const float4*)(g_z1 + (size_t)gr * D1 + c * 4);
        As[r][c * 4 + 0] = v.x; As[r][c * 4 + 1] = v.y;
        As[r][c * 4 + 2] = v.z; As[r][c * 4 + 3] = v.w;
    }
    __syncthreads();

    int row = tid & 63;
    int cg  = tid >> 6;
    float acc[10];
#pragma unroll
    for (int j = 0; j < 10; j++) acc[j] = 0.f;
#pragma unroll
    for (int k = 0; k < 64; k++) {
        float a = As[row][k];
#pragma unroll
        for (int j = 0; j < 10; j++) acc[j] += a * Bs[k][cg * 10 + j];
    }
    int gr = row0 + row;
    float ps = 0.f, pd = 0.f;
#pragma unroll
    for (int j = 0; j < 10; j++) {
        ps += acc[j] * __ldg(s2v + cg * 10 + j);
        pd += acc[j] * __ldg(d2v + cg * 10 + j);
    }
    sS[row][cg] = ps;
    sD[row][cg] = pd;
    if (gr < M) {
#pragma unroll
        for (int j = 0; j < 10; j++)
            g_h2[(size_t)gr * D2 + cg * 10 + j] = acc[j];
    }
    __syncthreads();
    if (tid < 64) {
        int grr = row0 + tid;
        if (grr < M) {
            g_as2[grr] = sS[tid][0] + sS[tid][1] + sS[tid][2] + sS[tid][3];
            g_ad2[grr] = sD[tid][0] + sD[tid][1] + sD[tid][2] + sD[tid][3];
        }
    }
}

// ---------------- layer-2 aggregate + log_softmax: HALF-WARP, idx prefetch -----
__global__ void k_agg2(const float* __restrict__ b2, float* __restrict__ out, int Nn) {
    int w = (blockIdx.x * blockDim.x + threadIdx.x) >> 5;
    int lane = threadIdx.x & 31;
    if (w * 2 >= Nn) return;
    int half = lane >> 4;
    int ll = lane & 15;
    bool act = (ll < 10);
    int lv = act ? ll : 0;
    int n = w * 2 + half;
    bool valid = (n < Nn);
    int nc = valid ? n : (Nn - 1);

    float adn = g_ad2[nc];

    float ex = __expf(lrelu(g_as2[nc] + adn));
    float4 hv = *(const float4*)(g_h2 + (size_t)nc * D2 + lv * 4);
    float ax = 0.f, ay = 0.f, az = 0.f, aw = 0.f;
    if (act) { ax = ex * hv.x; ay = ex * hv.y; az = ex * hv.z; aw = ex * hv.w; }
    float den = ex;

    int j = g_row[nc], end = g_row[nc + 1];
    int p0 = 0, p1 = 0;
    bool have = (j + 2 <= end);
    if (have) { p0 = __ldg(g_srt + j); p1 = __ldg(g_srt + j + 1); }
    while (have) {
        int jn = j + 2;
        bool haven = (jn + 2 <= end);
        int n0 = 0, n1 = 0;
        if (haven) { n0 = __ldg(g_srt + jn); n1 = __ldg(g_srt + jn + 1); }
        float x0 = __expf(lrelu(__ldg(g_as2 + p0) + adn));
        float x1 = __expf(lrelu(__ldg(g_as2 + p1) + adn));
        float4 v0 = *(const float4*)(g_h2 + (size_t)p0 * D2 + lv * 4);
        float4 v1 = *(const float4*)(g_h2 + (size_t)p1 * D2 + lv * 4);
        if (act) {
            ax += x0 * v0.x + x1 * v1.x;
            ay += x0 * v0.y + x1 * v1.y;
            az += x0 * v0.z + x1 * v1.z;
            aw += x0 * v0.w + x1 * v1.w;
        }
        den += x0 + x1;
        j = jn; p0 = n0; p1 = n1; have = haven;
    }
    for (; j < end; j++) {
        int s0 = __ldg(g_srt + j);
        float x0 = __expf(lrelu(__ldg(g_as2 + s0) + adn));
        float4 v0 = *(const float4*)(g_h2 + (size_t)s0 * D2 + lv * 4);
        if (act) {
            ax += x0 * v0.x; ay += x0 * v0.y; az += x0 * v0.z; aw += x0 * v0.w;
        }
        den += x0;
    }

    __syncwarp();
    float inv = 1.f / (den + 1e-16f);
    float4 bv = *(const float4*)(b2 + lv * 4);
    float vx = -3.4e38f, vy = -3.4e38f, vz = -3.4e38f, vw = -3.4e38f;
    if (act) {
        vx = ax * inv + bv.x;
        vy = ay * inv + bv.y;
        vz = az * inv + bv.z;
        vw = aw * inv + bv.w;
    }
    float m = fmaxf(fmaxf(vx, vy), fmaxf(vz, vw));
#pragma unroll
    for (int off = 8; off; off >>= 1) m = fmaxf(m, __shfl_xor_sync(0xffffffffu, m, off));
    float s = act ? (__expf(vx - m) + __expf(vy - m) + __expf(vz - m) + __expf(vw - m)) : 0.f;
#pragma unroll
    for (int off = 8; off; off >>= 1) s += __shfl_xor_sync(0xffffffffu, s, off);
    float l = m + logf(s);
    if (valid && act) {
        float4 o = make_float4(vx - l, vy - l, vz - l, vw - l);
        *(float4*)(out + (size_t)n * D2 + ll * 4) = o;
    }
}

// ---------------- launch: fork CSR || GEMM1(+att1), join at agg1 ----------------
extern "C" void kernel_launch(void* const* d_in, const int* in_sizes, int n_in,
                              void* d_out, int out_size) {
    const float* x   = (const float*)d_in[0];
    const int*   ei  = (const int*)d_in[1];       // int32 (JAX x64 disabled)
    const float* W1  = (const float*)d_in[2];
    const float* as1 = (const float*)d_in[3];
    const float* ad1 = (const float*)d_in[4];
    const float* b1  = (const float*)d_in[5];
    const float* W2  = (const float*)d_in[6];
    const float* as2 = (const float*)d_in[7];
    const float* ad2 = (const float*)d_in[8];
    const float* b2  = (const float*)d_in[9];

    int Nn = in_sizes[0] / FIN;      // 50000
    int E  = in_sizes[1] / 2;        // 1600000
    int nwarp = (Nn + 1) / 2;        // 2 nodes per warp
    int nb = (nwarp * 32 + 255) / 256;

    // Side stream + events, created per call. NOT destroyed (capture safety).
    cudaStream_t s2;
    cudaStreamCreateWithFlags(&s2, cudaStreamNonBlocking);
    cudaEvent_t eFork, eJoin;
    cudaEventCreateWithFlags(&eFork, cudaEventDisableTiming);
    cudaEventCreateWithFlags(&eJoin, cudaEventDisableTiming);

    cudaEventRecord(eFork, 0);
    cudaStreamWaitEvent(s2, eFork, 0);

    // branch B (side stream): CSR build (g_cnt pre-zeroed by module init / prior scanB)
    k_hist   <<<(E / 4 + 255) / 256, 256, 0, s2>>>(ei, E);
    k_scanA  <<<SCB, 256, 0, s2>>>();
    k_scanB  <<<SCB, 256, 0, s2>>>(Nn);
    // branch A (default stream): dense chain — issued 4th for the profiler slot
    k_gemm1  <<<(Nn + 127) / 128, 256>>>(x, W1, as1, ad1, Nn);
    k_scatter<<<(E + 255) / 256, 256, 0, s2>>>(ei, E);

    cudaEventRecord(eJoin, s2);
    cudaStreamWaitEvent(0, eJoin, 0);

    k_agg1   <<<nb, 256>>>(b1, Nn);
    k_gemm2  <<<(Nn + 63) / 64, 256>>>(W2, as2, ad2, Nn);
    k_agg2   <<<nb, 256>>>(b2, (float*)d_out, Nn);
}

// round 15
// speedup vs baseline: 1.2605x; 1.2605x over previous
#include <cuda_runtime.h>
#include <cuda_bf16.h>
#include <math.h>

// ---------------- problem constants ----------------
#define NMAX 50048            // N = 50000 nodes (padded)
#define EMAX 1600512
#define FIN  512
#define D1   64               // H1*hid = 8*8
#define H1N  8
#define D2   40               // C (H2=1)
#define SCB  196              // scan blocks: 196*256 = 50176 >= 50000
#define AROW 20               // smem row stride in b32 words (16 data + 4 pad)

// ---------------- scratch (device globals; no allocation allowed) ----------------
__device__ __align__(16) float g_h1 [NMAX * D1];   // x @ W1
__device__ __align__(16) float g_as1[NMAX * H1N];
__device__ __align__(16) float g_ad1[NMAX * H1N];
__device__ __align__(16) float g_z1 [NMAX * D1];   // relu(agg + b1): GEMM2 input
__device__ __align__(16) float g_h2 [NMAX * D2];
__device__ __align__(16) float g_as2[NMAX];
__device__ __align__(16) float g_ad2[NMAX];
// CSR-by-dst (built once per launch, shared by both layers)
__device__ int g_cnt[NMAX];      // zero-init at module load; scanB re-zeros after use
__device__ int g_row[NMAX + 1];
__device__ int g_cur[NMAX];
__device__ int g_part[SCB + 1];
__device__ int g_srt[EMAX];      // src ids, grouped by dst

__device__ __forceinline__ float lrelu(float v) { return (v >= 0.f) ? v : 0.2f * v; }
__device__ __forceinline__ unsigned packbf(float lo, float hi) {
    __nv_bfloat162 p = __floats2bfloat162_rn(lo, hi);   // .x = lo half
    return *(unsigned*)&p;
}

// ---------------- CSR build ------------------------------------------------------
__global__ void k_hist(const int* __restrict__ ei, int E) {
    int i4 = (blockIdx.x * blockDim.x + threadIdx.x) * 4;
    if (i4 + 3 < E) {
        int4 d = *(const int4*)(ei + E + i4);
        atomicAdd(&g_cnt[d.x], 1);
        atomicAdd(&g_cnt[d.y], 1);
        atomicAdd(&g_cnt[d.z], 1);
        atomicAdd(&g_cnt[d.w], 1);
    } else {
        for (int k = i4; k < E; k++) atomicAdd(&g_cnt[__ldg(ei + E + k)], 1);
    }
}
__global__ void k_scanA() {
    __shared__ int sh[256];
    int t = threadIdx.x, b = blockIdx.x;
    int i = b * 256 + t;
    int v = (i < NMAX) ? g_cnt[i] : 0;
    sh[t] = v;
    __syncthreads();
#pragma unroll
    for (int off = 128; off; off >>= 1) {
        if (t < off) sh[t] += sh[t + off];
        __syncthreads();
    }
    if (t == 0) g_part[b] = sh[0];
}
__global__ void k_scanB(int Nn) {
    __shared__ int part[256];
    __shared__ int sh[256];
    int t = threadIdx.x, b = blockIdx.x;
    part[t] = (t < SCB) ? g_part[t] : 0;
    __syncthreads();
    for (int off = 1; off < 256; off <<= 1) {
        int u = (t >= off) ? part[t - off] : 0;
        __syncthreads();
        part[t] += u;
        __syncthreads();
    }
    int base = (b == 0) ? 0 : part[b - 1];

    int i = b * 256 + t;
    int v = (i < NMAX) ? g_cnt[i] : 0;
    sh[t] = v;
    __syncthreads();
    for (int off = 1; off < 256; off <<= 1) {
        int u = (t >= off) ? sh[t - off] : 0;
        __syncthreads();
        sh[t] += u;
        __syncthreads();
    }
    int excl = sh[t] - v + base;
    if (i <= Nn) {
        g_row[i] = excl;
        if (i < Nn) g_cur[i] = excl;
    }
    if (i < NMAX) g_cnt[i] = 0;   // reset for the next graph replay
}
__global__ void k_scatter(const int* __restrict__ ei, int E) {
    int i = blockIdx.x * blockDim.x + threadIdx.x;
    if (i >= E) return;
    int s = __ldg(ei + i), d = __ldg(ei + E + i);
    int p = atomicAdd(&g_cur[d], 1);
    g_srt[p] = s;
}

// ---------------- GEMM1 (bf16 m16n8k16 MMA) + fused att1 ------------------------
// h1 = x @ W1 (fp32 accum); as1/ad1 via epilogue shfl.
// smem word layout: row of 16 b32 words (32 bf16), word w at p=(w&3)*4+(w>>2):
// one LDS.128 at p=lc*4 returns words {lc, lc+4, lc+8, lc+12} = both k-steps.
__global__ void __launch_bounds__(256) k_gemm1(
        const float* __restrict__ A, const float* __restrict__ B,
        const float* __restrict__ asrc, const float* __restrict__ adst, int M) {
    __shared__ __align__(16) unsigned As[128 * AROW];
    __shared__ __align__(16) unsigned Bs[64 * AROW];
    const int tid  = threadIdx.x;
    const int warp = tid >> 5, lane = tid & 31;
    const int row0 = blockIdx.x * 128;
    const int lr = lane >> 2, lc = lane & 3;

    float acc[8][4];
#pragma unroll
    for (int nt = 0; nt < 8; nt++)
#pragma unroll
        for (int j = 0; j < 4; j++) acc[nt][j] = 0.f;

    for (int k0 = 0; k0 < FIN; k0 += 32) {
        // A tile: 128 rows x 32 cols -> bf16 pairs; 1024 tasks (4 per thread)
#pragma unroll
        for (int i = 0; i < 4; i++) {
            int idx = tid + i * 256;
            int r = idx >> 3, c4 = idx & 7;
            float4 v = make_float4(0.f, 0.f, 0.f, 0.f);
            int gr = row0 + r;
            if (gr < M) v = *(const float4*)(A + (size_t)gr * FIN + k0 + c4 * 4);
            int wa = c4 * 2, wb = wa + 1;
            As[r * AROW + ((wa & 3) * 4 + (wa >> 2))] = packbf(v.x, v.y);
            As[r * AROW + ((wb & 3) * 4 + (wb >> 2))] = packbf(v.z, v.w);
        }
        // B tile: 32 k-rows x 64 cols; 256 tasks: kp (k-pair) x n4
        {
            int kp = tid >> 4, n4 = tid & 15;
            float4 g0 = *(const float4*)(B + (size_t)(k0 + 2 * kp) * D1 + n4 * 4);
            float4 g1 = *(const float4*)(B + (size_t)(k0 + 2 * kp + 1) * D1 + n4 * 4);
            int p = (kp & 3) * 4 + (kp >> 2);
            Bs[(n4 * 4 + 0) * AROW + p] = packbf(g0.x, g1.x);
            Bs[(n4 * 4 + 1) * AROW + p] = packbf(g0.y, g1.y);
            Bs[(n4 * 4 + 2) * AROW + p] = packbf(g0.z, g1.z);
            Bs[(n4 * 4 + 3) * AROW + p] = packbf(g0.w, g1.w);
        }
        __syncthreads();

        uint4 qa0 = *(const uint4*)&As[(warp * 16 + lr) * AROW + lc * 4];
        uint4 qa1 = *(const uint4*)&As[(warp * 16 + lr + 8) * AROW + lc * 4];
#pragma unroll
        for (int nt = 0; nt < 8; nt++) {
            uint4 qb = *(const uint4*)&Bs[(nt * 8 + lr) * AROW + lc * 4];
            asm volatile(
                "mma.sync.aligned.m16n8k16.row.col.f32.bf16.bf16.f32 "
                "{%0,%1,%2,%3}, {%4,%5,%6,%7}, {%8,%9}, {%0,%1,%2,%3};"
                : "+f"(acc[nt][0]), "+f"(acc[nt][1]), "+f"(acc[nt][2]), "+f"(acc[nt][3])
                : "r"(qa0.x), "r"(qa1.x), "r"(qa0.y), "r"(qa1.y),
                  "r"(qb.x), "r"(qb.y));
            asm volatile(
                "mma.sync.aligned.m16n8k16.row.col.f32.bf16.bf16.f32 "
                "{%0,%1,%2,%3}, {%4,%5,%6,%7}, {%8,%9}, {%0,%1,%2,%3};"
                : "+f"(acc[nt][0]), "+f"(acc[nt][1]), "+f"(acc[nt][2]), "+f"(acc[nt][3])
                : "r"(qa0.z), "r"(qa1.z), "r"(qa0.w), "r"(qa1.w),
                  "r"(qb.z), "r"(qb.w));
        }
        __syncthreads();
    }

    int gr = row0 + warp * 16 + lr;
#pragma unroll
    for (int nt = 0; nt < 8; nt++) {
        int col = nt * 8 + lc * 2;
        if (gr < M)     *(float2*)(g_h1 + (size_t)gr * D1 + col)       = make_float2(acc[nt][0], acc[nt][1]);
        if (gr + 8 < M) *(float2*)(g_h1 + (size_t)(gr + 8) * D1 + col) = make_float2(acc[nt][2], acc[nt][3]);

        // fused att1: head nt covers cols nt*8..nt*8+7; reduce across the lc quad
        float w0s = __ldg(asrc + nt * 8 + lc * 2), w1s = __ldg(asrc + nt * 8 + lc * 2 + 1);
        float w0d = __ldg(adst + nt * 8 + lc * 2), w1d = __ldg(adst + nt * 8 + lc * 2 + 1);
        float pSA = acc[nt][0] * w0s + acc[nt][1] * w1s;
        float pDA = acc[nt][0] * w0d + acc[nt][1] * w1d;
        float pSB = acc[nt][2] * w0s + acc[nt][3] * w1s;
        float pDB = acc[nt][2] * w0d + acc[nt][3] * w1d;
#pragma unroll
        for (int off = 1; off <= 2; off <<= 1) {
            pSA += __shfl_xor_sync(0xffffffffu, pSA, off);
            pDA += __shfl_xor_sync(0xffffffffu, pDA, off);
            pSB += __shfl_xor_sync(0xffffffffu, pSB, off);
            pDB += __shfl_xor_sync(0xffffffffu, pDB, off);
        }
        if (lc == 0) {
            if (gr < M)     { g_as1[gr * H1N + nt] = pSA;       g_ad1[gr * H1N + nt] = pDA; }
            if (gr + 8 < M) { g_as1[(gr + 8) * H1N + nt] = pSB; g_ad1[(gr + 8) * H1N + nt] = pDB; }
        }
    }
}

// ---------------- layer-1 aggregate: HALF-WARP per node, idx prefetch -----------
__global__ void k_agg1(const float* __restrict__ b1, int Nn) {
    int w = (blockIdx.x * blockDim.x + threadIdx.x) >> 5;
    int lane = threadIdx.x & 31;
    if (w * 2 >= Nn) return;              // uniform whole-warp exit
    int half = lane >> 4;
    int ll = lane & 15;
    int hh = ll >> 1;
    int n = w * 2 + half;
    bool valid = (n < Nn);
    int nc = valid ? n : (Nn - 1);

    float adh = g_ad1[nc * H1N + hh];

    float ex = __expf(lrelu(g_as1[nc * H1N + hh] + adh));
    float4 hv = *(const float4*)(g_h1 + (size_t)nc * D1 + ll * 4);
    float ax = ex * hv.x, ay = ex * hv.y, az = ex * hv.z, aw = ex * hv.w;
    float den = ((ll & 1) == 0) ? ex : 0.f;

    int j = g_row[nc], end = g_row[nc + 1];
    int p0 = 0, p1 = 0;
    bool have = (j + 2 <= end);
    if (have) { p0 = __ldg(g_srt + j); p1 = __ldg(g_srt + j + 1); }
    while (have) {
        int jn = j + 2;
        bool haven = (jn + 2 <= end);
        int n0 = 0, n1 = 0;
        if (haven) { n0 = __ldg(g_srt + jn); n1 = __ldg(g_srt + jn + 1); }
        float e0 = __ldg(g_as1 + p0 * H1N + hh) + adh;
        float e1 = __ldg(g_as1 + p1 * H1N + hh) + adh;
        float4 v0 = *(const float4*)(g_h1 + (size_t)p0 * D1 + ll * 4);
        float4 v1 = *(const float4*)(g_h1 + (size_t)p1 * D1 + ll * 4);
        float x0 = __expf(lrelu(e0)), x1 = __expf(lrelu(e1));
        ax += x0 * v0.x + x1 * v1.x;
        ay += x0 * v0.y + x1 * v1.y;
        az += x0 * v0.z + x1 * v1.z;
        aw += x0 * v0.w + x1 * v1.w;
        if ((ll & 1) == 0) den += x0 + x1;
        j = jn; p0 = n0; p1 = n1; have = haven;
    }
    for (; j < end; j++) {
        int s0 = __ldg(g_srt + j);
        float x0 = __expf(lrelu(__ldg(g_as1 + s0 * H1N + hh) + adh));
        float4 v0 = *(const float4*)(g_h1 + (size_t)s0 * D1 + ll * 4);
        ax += x0 * v0.x; ay += x0 * v0.y; az += x0 * v0.z; aw += x0 * v0.w;
        if ((ll & 1) == 0) den += x0;
    }

    __syncwarp();
    float dh = __shfl_sync(0xffffffffu, den, (lane & 16) | (ll & 0xe));
    float inv = 1.f / (dh + 1e-16f);
    float4 bv = *(const float4*)(b1 + ll * 4);
    if (valid) {
        float4 z;
        z.x = fmaxf(ax * inv + bv.x, 0.f);
        z.y = fmaxf(ay * inv + bv.y, 0.f);
        z.z = fmaxf(az * inv + bv.z, 0.f);
        z.w = fmaxf(aw * inv + bv.w, 0.f);
        *(float4*)(g_z1 + (size_t)n * D1 + ll * 4) = z;
    }
}

// ---------------- GEMM2 + fused att2: h2 = z1 @ W2 ------------------------------
__global__ void k_gemm2(const float* __restrict__ W2,
                        const float* __restrict__ s2v, const float* __restrict__ d2v,
                        int M) {
    __shared__ __align__(16) float As[64][65];
    __shared__ __align__(16) float Bs[64][D2];
    __shared__ float sS[64][4], sD[64][4];
    const int tid = threadIdx.x;
    const int row0 = blockIdx.x * 64;

    for (int idx = tid; idx < 64 * D2; idx += 256)
        Bs[idx / D2][idx % D2] = W2[idx];

#pragma unroll
    for (int i = 0; i < 4; i++) {
        int idx = tid + i * 256;
        int r = idx >> 4, c = idx & 15;
        int gr = row0 + r;
        float4 v = make_float4(0.f, 0.f, 0.f, 0.f);
        if (gr < M) v = *(const float4*)(g_z1 + (size_t)gr * D1 + c * 4);
        As[r][c * 4 + 0] = v.x; As[r][c * 4 + 1] = v.y;
        As[r][c * 4 + 2] = v.z; As[r][c * 4 + 3] = v.w;
    }
    __syncthreads();

    int row = tid & 63;
    int cg  = tid >> 6;
    float acc[10];
#pragma unroll
    for (int j = 0; j < 10; j++) acc[j] = 0.f;
#pragma unroll
    for (int k = 0; k < 64; k++) {
        float a = As[row][k];
#pragma unroll
        for (int j = 0; j < 10; j++) acc[j] += a * Bs[k][cg * 10 + j];
    }
    int gr = row0 + row;
    float ps = 0.f, pd = 0.f;
#pragma unroll
    for (int j = 0; j < 10; j++) {
        ps += acc[j] * __ldg(s2v + cg * 10 + j);
        pd += acc[j] * __ldg(d2v + cg * 10 + j);
    }
    sS[row][cg] = ps;
    sD[row][cg] = pd;
    if (gr < M) {
#pragma unroll
        for (int j = 0; j < 10; j++)
            g_h2[(size_t)gr * D2 + cg * 10 + j] = acc[j];
    }
    __syncthreads();
    if (tid < 64) {
        int grr = row0 + tid;
        if (grr < M) {
            g_as2[grr] = sS[tid][0] + sS[tid][1] + sS[tid][2] + sS[tid][3];
            g_ad2[grr] = sD[tid][0] + sD[tid][1] + sD[tid][2] + sD[tid][3];
        }
    }
}

// ---------------- layer-2 aggregate + log_softmax: HALF-WARP, idx prefetch -----
__global__ void k_agg2(const float* __restrict__ b2, float* __restrict__ out, int Nn) {
    int w = (blockIdx.x * blockDim.x + threadIdx.x) >> 5;
    int lane = threadIdx.x & 31;
    if (w * 2 >= Nn) return;
    int half = lane >> 4;
    int ll = lane & 15;
    bool act = (ll < 10);
    int lv = act ? ll : 0;
    int n = w * 2 + half;
    bool valid = (n < Nn);
    int nc = valid ? n : (Nn - 1);

    float adn = g_ad2[nc];

    float ex = __expf(lrelu(g_as2[nc] + adn));
    float4 hv = *(const float4*)(g_h2 + (size_t)nc * D2 + lv * 4);
    float ax = 0.f, ay = 0.f, az = 0.f, aw = 0.f;
    if (act) { ax = ex * hv.x; ay = ex * hv.y; az = ex * hv.z; aw = ex * hv.w; }
    float den = ex;

    int j = g_row[nc], end = g_row[nc + 1];
    int p0 = 0, p1 = 0;
    bool have = (j + 2 <= end);
    if (have) { p0 = __ldg(g_srt + j); p1 = __ldg(g_srt + j + 1); }
    while (have) {
        int jn = j + 2;
        bool haven = (jn + 2 <= end);
        int n0 = 0, n1 = 0;
        if (haven) { n0 = __ldg(g_srt + jn); n1 = __ldg(g_srt + jn + 1); }
        float x0 = __expf(lrelu(__ldg(g_as2 + p0) + adn));
        float x1 = __expf(lrelu(__ldg(g_as2 + p1) + adn));
        float4 v0 = *(const float4*)(g_h2 + (size_t)p0 * D2 + lv * 4);
        float4 v1 = *(const float4*)(g_h2 + (size_t)p1 * D2 + lv * 4);
        if (act) {
            ax += x0 * v0.x + x1 * v1.x;
            ay += x0 * v0.y + x1 * v1.y;
            az += x0 * v0.z + x1 * v1.z;
            aw += x0 * v0.w + x1 * v1.w;
        }
        den += x0 + x1;
        j = jn; p0 = n0; p1 = n1; have = haven;
    }
    for (; j < end; j++) {
        int s0 = __ldg(g_srt + j);
        float x0 = __expf(lrelu(__ldg(g_as2 + s0) + adn));
        float4 v0 = *(const float4*)(g_h2 + (size_t)s0 * D2 + lv * 4);
        if (act) {
            ax += x0 * v0.x; ay += x0 * v0.y; az += x0 * v0.z; aw += x0 * v0.w;
        }
        den += x0;
    }

    __syncwarp();
    float inv = 1.f / (den + 1e-16f);
    float4 bv = *(const float4*)(b2 + lv * 4);
    float vx = -3.4e38f, vy = -3.4e38f, vz = -3.4e38f, vw = -3.4e38f;
    if (act) {
        vx = ax * inv + bv.x;
        vy = ay * inv + bv.y;
        vz = az * inv + bv.z;
        vw = aw * inv + bv.w;
    }
    float m = fmaxf(fmaxf(vx, vy), fmaxf(vz, vw));
#pragma unroll
    for (int off = 8; off; off >>= 1) m = fmaxf(m, __shfl_xor_sync(0xffffffffu, m, off));
    float s = act ? (__expf(vx - m) + __expf(vy - m) + __expf(vz - m) + __expf(vw - m)) : 0.f;
#pragma unroll
    for (int off = 8; off; off >>= 1) s += __shfl_xor_sync(0xffffffffu, s, off);
    float l = m + logf(s);
    if (valid && act) {
        float4 o = make_float4(vx - l, vy - l, vz - l, vw - l);
        *(float4*)(out + (size_t)n * D2 + ll * 4) = o;
    }
}

// ---------------- launch: fork CSR || GEMM1(+att1), join at agg1 ----------------
extern "C" void kernel_launch(void* const* d_in, const int* in_sizes, int n_in,
                              void* d_out, int out_size) {
    const float* x   = (const float*)d_in[0];
    const int*   ei  = (const int*)d_in[1];       // int32 (JAX x64 disabled)
    const float* W1  = (const float*)d_in[2];
    const float* as1 = (const float*)d_in[3];
    const float* ad1 = (const float*)d_in[4];
    const float* b1  = (const float*)d_in[5];
    const float* W2  = (const float*)d_in[6];
    const float* as2 = (const float*)d_in[7];
    const float* ad2 = (const float*)d_in[8];
    const float* b2  = (const float*)d_in[9];

    int Nn = in_sizes[0] / FIN;      // 50000
    int E  = in_sizes[1] / 2;        // 1600000
    int nwarp = (Nn + 1) / 2;        // 2 nodes per warp
    int nb = (nwarp * 32 + 255) / 256;

    // Side stream + events, created per call. NOT destroyed (capture safety).
    cudaStream_t s2;
    cudaStreamCreateWithFlags(&s2, cudaStreamNonBlocking);
    cudaEvent_t eFork, eJoin;
    cudaEventCreateWithFlags(&eFork, cudaEventDisableTiming);
    cudaEventCreateWithFlags(&eJoin, cudaEventDisableTiming);

    cudaEventRecord(eFork, 0);
    cudaStreamWaitEvent(s2, eFork, 0);

    // branch B (side stream): CSR build (g_cnt pre-zeroed by module init / prior scanB)
    k_hist   <<<(E / 4 + 255) / 256, 256, 0, s2>>>(ei, E);
    k_scanA  <<<SCB, 256, 0, s2>>>();
    k_scanB  <<<SCB, 256, 0, s2>>>(Nn);
    // branch A (default stream): dense chain — gemm1 keeps the profiler slot (4th)
    k_gemm1  <<<(Nn + 127) / 128, 256>>>(x, W1, as1, ad1, Nn);
    k_scatter<<<(E + 255) / 256, 256, 0, s2>>>(ei, E);

    cudaEventRecord(eJoin, s2);
    cudaStreamWaitEvent(0, eJoin, 0);

    k_agg1   <<<nb, 256>>>(b1, Nn);
    k_gemm2  <<<(Nn + 63) / 64, 256>>>(W2, as2, ad2, Nn);
    k_agg2   <<<nb, 256>>>(b2, (float*)d_out, Nn);
}